// round 15
// baseline (speedup 1.0000x reference)
#include <cuda_runtime.h>
#include <cuda_fp16.h>
#include <math.h>
#include <float.h>

// Problem constants
#define B_   8
#define L_   2048
#define LOG2L 11
#define D_   512
#define DM_  512
#define KTOP 15

// ---------------- device scratch (static allocation only) ----------------
__device__ float g_qT[B_ * D_ * L_];   // (B, D, L)
__device__ float g_kT[B_ * D_ * L_];
__device__ float g_vT[B_ * D_ * L_];
__device__ float g_AT[B_ * D_ * L_];
__device__ float2 g_tw[L_ / 2];        // exp(-2*pi*i*j/L)

// ---------------- twiddle init ----------------
__global__ void twiddle_init_kernel() {
    int j = blockIdx.x * blockDim.x + threadIdx.x;
    if (j < L_ / 2) {
        float sn, cs;
        sincospif((float)j / 1024.0f, &sn, &cs);
        g_tw[j] = make_float2(cs, -sn);
    }
}

// ---------------- FP16 split helpers ----------------
__device__ __forceinline__ unsigned pack_hi(float a, float b) {
    __half2 h = __halves2half2(__float2half_rn(a), __float2half_rn(b));
    return *(unsigned*)&h;
}
__device__ __forceinline__ unsigned pack_lo(float a, float b) {
    float ra = a - __half2float(__float2half_rn(a));
    float rb = b - __half2float(__float2half_rn(b));
    __half2 h = __halves2half2(__float2half_rn(ra), __float2half_rn(rb));
    return *(unsigned*)&h;
}

__device__ __forceinline__ void mma_f16(float c[4], const unsigned a[4], const unsigned b[2]) {
    asm volatile(
        "mma.sync.aligned.m16n8k16.row.col.f32.f16.f16.f32 "
        "{%0,%1,%2,%3}, {%4,%5,%6,%7}, {%8,%9}, {%0,%1,%2,%3};\n"
        : "+f"(c[0]), "+f"(c[1]), "+f"(c[2]), "+f"(c[3])
        : "r"(a[0]), "r"(a[1]), "r"(a[2]), "r"(a[3]), "r"(b[0]), "r"(b[1]));
}

// ---------------- Fused 3-GEMM (fp16 split x3, K-tile 32: half the barriers) ----
// out^T[b,d,t] = X @ W + bias. CTA tile 128(t) x 128(d), K-tile 32 (2 k-steps).
// 8 warps as 2(m) x 4(n); warp tile 64x32; mma m16n8k16. Fragment scheme = r5.
__global__ __launch_bounds__(256, 2)
void gemm3_fp16_kernel(const float* __restrict__ Qi, const float* __restrict__ Ki,
                       const float* __restrict__ Vi,
                       const float* __restrict__ WQ, const float* __restrict__ WK,
                       const float* __restrict__ WV,
                       const float* __restrict__ bQ, const float* __restrict__ bK,
                       const float* __restrict__ bV) {
    const int z = blockIdx.z;
    const float* X    = (z == 0) ? Qi : ((z == 1) ? Ki : Vi);
    const float* W    = (z == 0) ? WQ : ((z == 1) ? WK : WV);
    const float* bias = (z == 0) ? bQ : ((z == 1) ? bK : bV);
    float* outT       = (z == 0) ? g_qT : ((z == 1) ? g_kT : g_vT);

    // 16 kpairs used, rows padded to 20 words (80B: 16B-aligned, conflict-free frags)
    __shared__ unsigned As2h[128][20], As2l[128][20];
    __shared__ unsigned Bs2h[16][132], Bs2l[16][132];

    const int tid = threadIdx.x;
    const int lane = tid & 31;
    const int w = tid >> 5;
    const int wm0 = (w & 1) * 64;
    const int wn0 = (w >> 1) * 32;
    const int g = lane >> 2;    // 0..7
    const int c = lane & 3;     // 0..3
    const int m0 = blockIdx.x * 128;
    const int n0 = blockIdx.y * 128;

    // global load mapping (K-tile 32)
    const int rowA = tid >> 1;             // 0..127
    const int kbA  = (tid & 1) * 16;       // k base within 32
    const int kpA  = (tid & 1) * 8;        // kpair base in smem
    const int prB  = tid >> 4;             // 0..15 (kpair row)
    const int nqB  = (tid & 15) * 8;       // 0..120
    const float* pA  = &X[(size_t)(m0 + rowA) * DM_ + kbA];
    const float* pB0 = &W[(size_t)(2 * prB) * D_ + n0 + nqB];
    const float* pB1 = pB0 + D_;

    float cacc[4][4][4];
#pragma unroll
    for (int mt = 0; mt < 4; mt++)
#pragma unroll
        for (int nt = 0; nt < 4; nt++)
#pragma unroll
            for (int i = 0; i < 4; i++) cacc[mt][nt][i] = 0.0f;

    float4 a0 = *(const float4*)pA;
    float4 a1 = *(const float4*)(pA + 4);
    float4 a2 = *(const float4*)(pA + 8);
    float4 a3 = *(const float4*)(pA + 12);
    float4 b00 = *(const float4*)pB0;
    float4 b01 = *(const float4*)(pB0 + 4);
    float4 b10 = *(const float4*)pB1;
    float4 b11 = *(const float4*)(pB1 + 4);

#pragma unroll 1
    for (int k0 = 0; k0 < DM_; k0 += 32) {
        // pack current tile into half2 hi/lo (uint4 stores, aligned)
        {
            uint4 h0 = make_uint4(pack_hi(a0.x, a0.y), pack_hi(a0.z, a0.w),
                                  pack_hi(a1.x, a1.y), pack_hi(a1.z, a1.w));
            uint4 h1 = make_uint4(pack_hi(a2.x, a2.y), pack_hi(a2.z, a2.w),
                                  pack_hi(a3.x, a3.y), pack_hi(a3.z, a3.w));
            uint4 l0 = make_uint4(pack_lo(a0.x, a0.y), pack_lo(a0.z, a0.w),
                                  pack_lo(a1.x, a1.y), pack_lo(a1.z, a1.w));
            uint4 l1 = make_uint4(pack_lo(a2.x, a2.y), pack_lo(a2.z, a2.w),
                                  pack_lo(a3.x, a3.y), pack_lo(a3.z, a3.w));
            *(uint4*)&As2h[rowA][kpA]     = h0;
            *(uint4*)&As2h[rowA][kpA + 4] = h1;
            *(uint4*)&As2l[rowA][kpA]     = l0;
            *(uint4*)&As2l[rowA][kpA + 4] = l1;
            uint4 bh0 = make_uint4(pack_hi(b00.x, b10.x), pack_hi(b00.y, b10.y),
                                   pack_hi(b00.z, b10.z), pack_hi(b00.w, b10.w));
            uint4 bh1 = make_uint4(pack_hi(b01.x, b11.x), pack_hi(b01.y, b11.y),
                                   pack_hi(b01.z, b11.z), pack_hi(b01.w, b11.w));
            uint4 bl0 = make_uint4(pack_lo(b00.x, b10.x), pack_lo(b00.y, b10.y),
                                   pack_lo(b00.z, b10.z), pack_lo(b00.w, b10.w));
            uint4 bl1 = make_uint4(pack_lo(b01.x, b11.x), pack_lo(b01.y, b11.y),
                                   pack_lo(b01.z, b11.z), pack_lo(b01.w, b11.w));
            *(uint4*)&Bs2h[prB][nqB]     = bh0;
            *(uint4*)&Bs2h[prB][nqB + 4] = bh1;
            *(uint4*)&Bs2l[prB][nqB]     = bl0;
            *(uint4*)&Bs2l[prB][nqB + 4] = bl1;
        }
        __syncthreads();

        // prefetch next k-tile (hidden under the 96-MMA phase)
        if (k0 + 32 < DM_) {
            const int ko = k0 + 32;
            a0 = *(const float4*)(pA + ko);
            a1 = *(const float4*)(pA + ko + 4);
            a2 = *(const float4*)(pA + ko + 8);
            a3 = *(const float4*)(pA + ko + 12);
            const float* qB0 = pB0 + (size_t)ko * D_;
            b00 = *(const float4*)qB0;
            b01 = *(const float4*)(qB0 + 4);
            b10 = *(const float4*)(qB0 + D_);
            b11 = *(const float4*)(qB0 + D_ + 4);
        }

        // 2 k-steps of fragments + MMAs
#pragma unroll
        for (int ks = 0; ks < 2; ks++) {
            const int kb = ks * 8;
            unsigned bh[4][2], bl[4][2];
#pragma unroll
            for (int nt = 0; nt < 4; nt++) {
                int cn = wn0 + nt * 8 + g;
                bh[nt][0] = Bs2h[kb + c][cn];
                bh[nt][1] = Bs2h[kb + c + 4][cn];
                bl[nt][0] = Bs2l[kb + c][cn];
                bl[nt][1] = Bs2l[kb + c + 4][cn];
            }
#pragma unroll
            for (int mt = 0; mt < 4; mt++) {
                int row = wm0 + mt * 16 + g;
                unsigned ah[4], al[4];
                ah[0] = As2h[row][kb + c];
                ah[1] = As2h[row + 8][kb + c];
                ah[2] = As2h[row][kb + c + 4];
                ah[3] = As2h[row + 8][kb + c + 4];
                al[0] = As2l[row][kb + c];
                al[1] = As2l[row + 8][kb + c];
                al[2] = As2l[row][kb + c + 4];
                al[3] = As2l[row + 8][kb + c + 4];
#pragma unroll
                for (int nt = 0; nt < 4; nt++) {
                    mma_f16(cacc[mt][nt], ah, bl[nt]);
                    mma_f16(cacc[mt][nt], al, bh[nt]);
                    mma_f16(cacc[mt][nt], ah, bh[nt]);
                }
            }
        }
        __syncthreads();
    }

    // epilogue: bias + transposed store
    const int b = m0 >> LOG2L;
    const int tbase = (m0 & (L_ - 1)) + wm0 + g;
#pragma unroll
    for (int nt = 0; nt < 4; nt++) {
        const int d0 = n0 + wn0 + nt * 8 + 2 * c;
        const float bi0 = bias[d0];
        const float bi1 = bias[d0 + 1];
        const size_t row0 = ((size_t)(b * D_ + d0) << LOG2L);
        const size_t row1 = row0 + L_;
#pragma unroll
        for (int mt = 0; mt < 4; mt++) {
            const int t = tbase + mt * 16;
            outT[row0 + t]     = cacc[mt][nt][0] + bi0;
            outT[row1 + t]     = cacc[mt][nt][1] + bi1;
            outT[row0 + t + 8] = cacc[mt][nt][2] + bi0;
            outT[row1 + t + 8] = cacc[mt][nt][3] + bi1;
        }
    }
}

// ---------------- complex helpers ----------------
__device__ __forceinline__ float2 cmul(float2 a, float2 b) {
    return make_float2(a.x * b.x - a.y * b.y, a.x * b.y + a.y * b.x);
}
__device__ __forceinline__ float2 cmulc(float2 a, float2 b) {   // a * conj(b)
    return make_float2(a.x * b.x + a.y * b.y, a.y * b.x - a.x * b.y);
}
__device__ __forceinline__ float2 cadd(float2 a, float2 b) { return make_float2(a.x + b.x, a.y + b.y); }
__device__ __forceinline__ float2 csub(float2 a, float2 b) { return make_float2(a.x - b.x, a.y - b.y); }

#define ZI(i) ((i) + ((i) >> 5))
#define XI(i) ((i) + ((i) >> 5))

#define BF_F(A, B, W) do { float2 _t = csub(A, B); A = cadd(A, B); B = cmul(_t, W); } while (0)
#define BF_I(A, B, W) do { float2 _bw = cmulc(B, W); B = csub(A, _bw); A = cadd(A, _bw); } while (0)

// ---------------- fused FFT-correlation + top-k + softmax + gather ----------------
// EXACT r14 champion: 128 threads, 16 pts/thread forward, half-size inverse.
__global__ __launch_bounds__(128)
void corr_attn_kernel() {
    __shared__ float2 tw[L_ / 2];
    __shared__ float2 z[L_ + L_ / 32];
    __shared__ float2 s[L_ + L_ / 32];
    __shared__ float  red_v[8];
    __shared__ int    red_i[8];

    const int tid = threadIdx.x;           // 0..127
    const int lane = tid & 31;
    const int warp = tid >> 5;              // 0..3
    const int bd = blockIdx.x;
    const size_t col = (size_t)bd << LOG2L;

    float2* zx = z + 1056;

    for (int i = tid; i < L_ / 2; i += 128) tw[i] = g_tw[i];

    float2 zr[16];
#pragma unroll
    for (int q = 0; q < 16; q++)
        zr[q] = make_float2(g_qT[col + tid + 128 * q], g_kT[col + tid + 128 * q]);
    __syncthreads();

    // ======== forward DIF, group 1: spans 1024/512/256/128 ========
#pragma unroll
    for (int q = 0; q < 8; q++) {
        float2 wv = tw[tid + 128 * q];
        BF_F(zr[q], zr[q + 8], wv);
    }
#pragma unroll
    for (int h = 0; h < 16; h += 8)
#pragma unroll
        for (int q = 0; q < 4; q++) {
            float2 wv = tw[(tid + 128 * q) << 1];
            BF_F(zr[h + q], zr[h + q + 4], wv);
        }
#pragma unroll
    for (int h = 0; h < 16; h += 4)
#pragma unroll
        for (int q = 0; q < 2; q++) {
            float2 wv = tw[(tid + 128 * q) << 2];
            BF_F(zr[h + q], zr[h + q + 2], wv);
        }
    {
        float2 wv = tw[tid << 3];
#pragma unroll
        for (int p = 0; p < 16; p += 2) BF_F(zr[p], zr[p + 1], wv);
    }
#pragma unroll
    for (int q = 0; q < 16; q++) s[ZI(tid + 128 * q)] = zr[q];
    __syncthreads();

    // ======== group 2: spans 64/32/16/8 ========
    const int c8 = (tid & 7) + (tid >> 3) * 128;
#pragma unroll
    for (int q = 0; q < 16; q++) zr[q] = s[ZI(c8 + 8 * q)];
#pragma unroll
    for (int q = 0; q < 8; q++) {
        float2 wv = tw[((tid & 7) + 8 * q) << 4];
        BF_F(zr[q], zr[q + 8], wv);
    }
#pragma unroll
    for (int h = 0; h < 16; h += 8)
#pragma unroll
        for (int q = 0; q < 4; q++) {
            float2 wv = tw[((tid & 7) + 8 * q) << 5];
            BF_F(zr[h + q], zr[h + q + 4], wv);
        }
#pragma unroll
    for (int h = 0; h < 16; h += 4)
#pragma unroll
        for (int q = 0; q < 2; q++) {
            float2 wv = tw[((tid & 7) + 8 * q) << 6];
            BF_F(zr[h + q], zr[h + q + 2], wv);
        }
    {
        float2 wv = tw[(tid & 7) << 7];
#pragma unroll
        for (int p = 0; p < 16; p += 2) BF_F(zr[p], zr[p + 1], wv);
    }
#pragma unroll
    for (int q = 0; q < 16; q++) s[ZI(c8 + 8 * q)] = zr[q];
    __syncthreads();

    // ======== group 3: spans 4/2/1 ========
    const int base16 = tid * 16;
#pragma unroll
    for (int q = 0; q < 16; q++) zr[q] = s[ZI(base16 + q)];
#pragma unroll
    for (int h = 0; h < 16; h += 8)
#pragma unroll
        for (int q = 0; q < 4; q++) {
            float2 wv = tw[q << 8];
            BF_F(zr[h + q], zr[h + q + 4], wv);
        }
#pragma unroll
    for (int h = 0; h < 16; h += 4)
#pragma unroll
        for (int q = 0; q < 2; q++) {
            float2 wv = tw[q << 9];
            BF_F(zr[h + q], zr[h + q + 2], wv);
        }
#pragma unroll
    for (int p = 0; p < 16; p += 2) {
        float2 a = zr[p], b = zr[p + 1];
        zr[p] = cadd(a, b);
        zr[p + 1] = csub(a, b);
    }
#pragma unroll
    for (int q = 0; q < 16; q++) s[ZI(base16 + q)] = zr[q];
    __syncthreads();

    // ======== cross-spectrum: s -> z ========
    const float scl = 0.25f / (float)L_;
#pragma unroll
    for (int it = 0; it < 16; it++) {
        int p = tid + 128 * it;
        int f = __brev((unsigned)p) >> 21;
        int fm = (L_ - f) & (L_ - 1);
        int pm = __brev((unsigned)fm) >> 21;
        float2 Zf = s[ZI(p)], Zm = s[ZI(pm)];
        float2 u = make_float2(Zf.x + Zm.x, Zf.y - Zm.y);
        float2 v = make_float2(Zf.x - Zm.x, -Zf.y - Zm.y);
        float2 pr = cmul(u, v);
        z[ZI(p)] = make_float2(-pr.y * scl, pr.x * scl);
    }
    __syncthreads();

    // ======== fused combine + inverse group A ========
    float2 X[8];
    {
        float2 Sp[16];
#pragma unroll
        for (int e = 0; e < 16; e++) Sp[e] = z[ZI(base16 + e)];
#pragma unroll
        for (int cc = 0; cc < 8; cc++) {
            int j = 8 * tid + cc;
            int k = __brev((unsigned)j) >> 22;
            float2 E = cadd(Sp[2 * cc], Sp[2 * cc + 1]);
            float2 Dd = csub(Sp[2 * cc], Sp[2 * cc + 1]);
            float2 O = cmulc(Dd, tw[k]);
            X[cc] = make_float2(E.x - O.y, E.y + O.x);
        }
#pragma unroll
        for (int p = 0; p < 8; p += 2) {
            float2 a = X[p], b = X[p + 1];
            X[p] = cadd(a, b);
            X[p + 1] = csub(a, b);
        }
#pragma unroll
        for (int h = 0; h < 8; h += 4)
#pragma unroll
            for (int q = 0; q < 2; q++) {
                float2 wv = tw[q << 9];
                BF_I(X[h + q], X[h + q + 2], wv);
            }
    }
    __syncthreads();
#pragma unroll
    for (int cc = 0; cc < 8; cc++) zx[XI(8 * tid + cc)] = X[cc];

    float* vcol = (float*)z;
    for (int i = tid; i < L_; i += 128) vcol[i] = g_vT[col + i];
    __syncthreads();

    // ======== inverse group B: spans 4/8/16 ========
    {
        const int c4b = (tid & 3) + (tid >> 2) * 32;
        float2 xr[8];
#pragma unroll
        for (int q = 0; q < 8; q++) xr[q] = zx[XI(c4b + 4 * q)];
        {
            float2 wv = tw[(tid & 3) << 8];
#pragma unroll
            for (int p = 0; p < 8; p += 2) BF_I(xr[p], xr[p + 1], wv);
        }
#pragma unroll
        for (int h = 0; h < 8; h += 4)
#pragma unroll
            for (int q = 0; q < 2; q++) {
                float2 wv = tw[((tid & 3) + 4 * q) << 7];
                BF_I(xr[h + q], xr[h + q + 2], wv);
            }
#pragma unroll
        for (int q = 0; q < 4; q++) {
            float2 wv = tw[((tid & 3) + 4 * q) << 6];
            BF_I(xr[q], xr[q + 4], wv);
        }
#pragma unroll
        for (int q = 0; q < 8; q++) zx[XI(c4b + 4 * q)] = xr[q];
    }
    __syncthreads();

    // ======== inverse group C: spans 32/64/128 ========
    {
        const int c32b = (tid & 31) + (tid >> 5) * 256;
        float2 xr[8];
#pragma unroll
        for (int q = 0; q < 8; q++) xr[q] = zx[XI(c32b + 32 * q)];
        {
            float2 wv = tw[(tid & 31) << 5];
#pragma unroll
            for (int p = 0; p < 8; p += 2) BF_I(xr[p], xr[p + 1], wv);
        }
#pragma unroll
        for (int h = 0; h < 8; h += 4)
#pragma unroll
            for (int q = 0; q < 2; q++) {
                float2 wv = tw[((tid & 31) + 32 * q) << 4];
                BF_I(xr[h + q], xr[h + q + 2], wv);
            }
#pragma unroll
        for (int q = 0; q < 4; q++) {
            float2 wv = tw[((tid & 31) + 32 * q) << 3];
            BF_I(xr[q], xr[q + 4], wv);
        }
#pragma unroll
        for (int q = 0; q < 8; q++) zx[XI(c32b + 32 * q)] = xr[q];
    }
    __syncthreads();

    // ======== inverse group D: spans 256/512 (registers; feeds top-k) ========
    float2 xr[8];
#pragma unroll
    for (int q = 0; q < 8; q++) xr[q] = zx[XI(tid + 128 * q)];
#pragma unroll
    for (int h = 0; h < 8; h += 4)
#pragma unroll
        for (int q = 0; q < 2; q++) {
            float2 wv = tw[(tid + 128 * q) << 2];
            BF_I(xr[h + q], xr[h + q + 2], wv);
        }
#pragma unroll
    for (int q = 0; q < 4; q++) {
        float2 wv = tw[(tid + 128 * q) << 1];
        BF_I(xr[q], xr[q + 4], wv);
    }

    // ---- top-15; idx = 2*tid + 256*q + comp ----
    float rv[16];
#pragma unroll
    for (int q = 0; q < 8; q++) { rv[2 * q] = xr[q].x; rv[2 * q + 1] = xr[q].y; }

    float wsel[KTOP];
    int isel[KTOP];
#pragma unroll 1
    for (int rnd = 0; rnd < KTOP; rnd++) {
        float best = rv[0];
        int bq = 0;
#pragma unroll
        for (int q = 1; q < 16; q++)
            if (rv[q] > best) { best = rv[q]; bq = q; }
        int bi = 2 * tid + 256 * (bq >> 1) + (bq & 1);
#pragma unroll
        for (int off = 16; off > 0; off >>= 1) {
            float ov = __shfl_xor_sync(0xffffffffu, best, off);
            int oi = __shfl_xor_sync(0xffffffffu, bi, off);
            if (ov > best || (ov == best && oi < bi)) { best = ov; bi = oi; }
        }
        const int slot = (rnd & 1) * 4;
        if (lane == 0) { red_v[slot + warp] = best; red_i[slot + warp] = bi; }
        __syncthreads();
        float gb = red_v[slot];
        int gi = red_i[slot];
#pragma unroll
        for (int ww = 1; ww < 4; ww++) {
            float ov = red_v[slot + ww];
            int oi = red_i[slot + ww];
            if (ov > gb || (ov == gb && oi < gi)) { gb = ov; gi = oi; }
        }
        wsel[rnd] = gb;
        isel[rnd] = gi;
#pragma unroll
        for (int q = 0; q < 8; q++) {
            if (gi == 2 * tid + 256 * q)     rv[2 * q]     = -FLT_MAX;
            if (gi == 2 * tid + 256 * q + 1) rv[2 * q + 1] = -FLT_MAX;
        }
    }

    // ---- softmax ----
    float m = wsel[0];
#pragma unroll
    for (int k = 1; k < KTOP; k++) m = fmaxf(m, wsel[k]);
    float sum = 0.0f;
    float wnorm[KTOP];
#pragma unroll
    for (int k = 0; k < KTOP; k++) { float e = __expf(wsel[k] - m); wnorm[k] = e; sum += e; }
    const float inv = 1.0f / sum;
#pragma unroll
    for (int k = 0; k < KTOP; k++) wnorm[k] *= inv;

    // ---- gather ----
    for (int l = tid; l < L_; l += 128) {
        float acc = 0.0f;
#pragma unroll
        for (int k = 0; k < KTOP; k++)
            acc = fmaf(wnorm[k], vcol[(l + isel[k]) & (L_ - 1)], acc);
        g_AT[col + l] = acc;
    }
}

// ---------------- transpose (B, D, L) -> (B, L, D) ----------------
__global__ void transpose_kernel(float* __restrict__ A) {
    __shared__ float tile[32][33];
    const int b = blockIdx.z;
    const int l0 = blockIdx.x * 32;
    const int d0 = blockIdx.y * 32;
    const int tx = threadIdx.x, ty = threadIdx.y;
#pragma unroll
    for (int r = 0; r < 32; r += 8)
        tile[ty + r][tx] = g_AT[((size_t)(b * D_ + d0 + ty + r) << LOG2L) + l0 + tx];
    __syncthreads();
#pragma unroll
    for (int r = 0; r < 32; r += 8)
        A[((size_t)(b * L_ + l0 + ty + r)) * D_ + d0 + tx] = tile[tx][ty + r];
}

// ---------------- launch ----------------
extern "C" void kernel_launch(void* const* d_in, const int* in_sizes, int n_in,
                              void* d_out, int out_size) {
    const float* Q   = (const float*)d_in[0];
    const float* K   = (const float*)d_in[1];
    const float* V   = (const float*)d_in[2];
    const float* WQw = (const float*)d_in[3];
    const float* WQb = (const float*)d_in[4];
    const float* WKw = (const float*)d_in[5];
    const float* WKb = (const float*)d_in[6];
    const float* WVw = (const float*)d_in[7];
    const float* WVb = (const float*)d_in[8];
    float* out = (float*)d_out;

    twiddle_init_kernel<<<4, 256>>>();

    dim3 ggrid(B_ * L_ / 128, D_ / 128, 3);   // (128, 4, 3)
    gemm3_fp16_kernel<<<ggrid, 256>>>(Q, K, V, WQw, WKw, WVw, WQb, WKb, WVb);

    corr_attn_kernel<<<B_ * D_, 128>>>();

    dim3 tgrid(L_ / 32, D_ / 32, B_);         // (64, 16, 8)
    transpose_kernel<<<tgrid, dim3(32, 8)>>>(out);
}

// round 16
// speedup vs baseline: 1.1534x; 1.1534x over previous
#include <cuda_runtime.h>
#include <cuda_fp16.h>
#include <math.h>
#include <float.h>

// Problem constants
#define B_   8
#define L_   2048
#define LOG2L 11
#define D_   512
#define DM_  512
#define KTOP 15

// ---------------- device scratch (static allocation only) ----------------
__device__ float g_qT[B_ * D_ * L_];   // (B, D, L)
__device__ float g_kT[B_ * D_ * L_];
__device__ float g_vT[B_ * D_ * L_];
__device__ float g_AT[B_ * D_ * L_];
__device__ float2 g_tw[L_ / 2];        // exp(-2*pi*i*j/L)

// ---------------- twiddle init ----------------
__global__ void twiddle_init_kernel() {
    int j = blockIdx.x * blockDim.x + threadIdx.x;
    if (j < L_ / 2) {
        float sn, cs;
        sincospif((float)j / 1024.0f, &sn, &cs);
        g_tw[j] = make_float2(cs, -sn);
    }
}

// ---------------- FP16 split helpers ----------------
__device__ __forceinline__ unsigned pack_hi(float a, float b) {
    __half2 h = __halves2half2(__float2half_rn(a), __float2half_rn(b));
    return *(unsigned*)&h;
}
__device__ __forceinline__ unsigned pack_lo(float a, float b) {
    float ra = a - __half2float(__float2half_rn(a));
    float rb = b - __half2float(__float2half_rn(b));
    __half2 h = __halves2half2(__float2half_rn(ra), __float2half_rn(rb));
    return *(unsigned*)&h;
}

__device__ __forceinline__ void mma_f16(float c[4], const unsigned a[4], const unsigned b[2]) {
    asm volatile(
        "mma.sync.aligned.m16n8k16.row.col.f32.f16.f16.f32 "
        "{%0,%1,%2,%3}, {%4,%5,%6,%7}, {%8,%9}, {%0,%1,%2,%3};\n"
        : "+f"(c[0]), "+f"(c[1]), "+f"(c[2]), "+f"(c[3])
        : "r"(a[0]), "r"(a[1]), "r"(a[2]), "r"(a[3]), "r"(b[0]), "r"(b[1]));
}

// ---------------- Fused 3-GEMM (fp16 split x3 products, fp32 accum) ----------------
// EXACT r5 champion version — FROZEN. out^T[b,d,t] = X @ W + bias.
// CTA tile 128(t) x 128(d), K-tile 16. 8 warps as 2(m) x 4(n); warp tile 64x32.
__global__ __launch_bounds__(256, 2)
void gemm3_fp16_kernel(const float* __restrict__ Qi, const float* __restrict__ Ki,
                       const float* __restrict__ Vi,
                       const float* __restrict__ WQ, const float* __restrict__ WK,
                       const float* __restrict__ WV,
                       const float* __restrict__ bQ, const float* __restrict__ bK,
                       const float* __restrict__ bV) {
    const int z = blockIdx.z;
    const float* X    = (z == 0) ? Qi : ((z == 1) ? Ki : Vi);
    const float* W    = (z == 0) ? WQ : ((z == 1) ? WK : WV);
    const float* bias = (z == 0) ? bQ : ((z == 1) ? bK : bV);
    float* outT       = (z == 0) ? g_qT : ((z == 1) ? g_kT : g_vT);

    __shared__ unsigned As2h[128][9], As2l[128][9];
    __shared__ unsigned Bs2h[8][132], Bs2l[8][132];

    const int tid = threadIdx.x;
    const int lane = tid & 31;
    const int w = tid >> 5;
    const int wm0 = (w & 1) * 64;
    const int wn0 = (w >> 1) * 32;
    const int g = lane >> 2;    // 0..7
    const int c = lane & 3;     // 0..3
    const int m0 = blockIdx.x * 128;
    const int n0 = blockIdx.y * 128;

    const int rowA = tid >> 2;             // 0..63 (and +64)
    const int kqA  = (tid & 3) << 2;       // 0,4,8,12
    const int pB   = tid >> 5;             // 0..7 (kpair)
    const int nqB  = (lane) << 2;          // 0..124
    const float* pA0 = &X[(size_t)(m0 + rowA) * DM_ + kqA];
    const float* pA1 = pA0 + (size_t)64 * DM_;
    const float* pB0 = &W[(size_t)(2 * pB) * D_ + n0 + nqB];
    const float* pB1 = pB0 + D_;

    float cacc[4][4][4];
#pragma unroll
    for (int mt = 0; mt < 4; mt++)
#pragma unroll
        for (int nt = 0; nt < 4; nt++)
#pragma unroll
            for (int i = 0; i < 4; i++) cacc[mt][nt][i] = 0.0f;

    float4 av0 = *(const float4*)pA0;
    float4 av1 = *(const float4*)pA1;
    float4 bv0 = *(const float4*)pB0;
    float4 bv1 = *(const float4*)pB1;

#pragma unroll 1
    for (int k0 = 0; k0 < DM_; k0 += 16) {
        const int kp = kqA >> 1;
        As2h[rowA][kp]          = pack_hi(av0.x, av0.y);
        As2h[rowA][kp + 1]      = pack_hi(av0.z, av0.w);
        As2l[rowA][kp]          = pack_lo(av0.x, av0.y);
        As2l[rowA][kp + 1]      = pack_lo(av0.z, av0.w);
        As2h[rowA + 64][kp]     = pack_hi(av1.x, av1.y);
        As2h[rowA + 64][kp + 1] = pack_hi(av1.z, av1.w);
        As2l[rowA + 64][kp]     = pack_lo(av1.x, av1.y);
        As2l[rowA + 64][kp + 1] = pack_lo(av1.z, av1.w);
        {
            uint4 uh = make_uint4(pack_hi(bv0.x, bv1.x), pack_hi(bv0.y, bv1.y),
                                  pack_hi(bv0.z, bv1.z), pack_hi(bv0.w, bv1.w));
            uint4 ul = make_uint4(pack_lo(bv0.x, bv1.x), pack_lo(bv0.y, bv1.y),
                                  pack_lo(bv0.z, bv1.z), pack_lo(bv0.w, bv1.w));
            *(uint4*)&Bs2h[pB][nqB] = uh;
            *(uint4*)&Bs2l[pB][nqB] = ul;
        }
        __syncthreads();

        if (k0 + 16 < DM_) {
            av0 = *(const float4*)(pA0 + k0 + 16);
            av1 = *(const float4*)(pA1 + k0 + 16);
            bv0 = *(const float4*)(pB0 + (size_t)(k0 + 16) * D_);
            bv1 = *(const float4*)(pB1 + (size_t)(k0 + 16) * D_);
        }

        unsigned bh[4][2], bl[4][2];
#pragma unroll
        for (int nt = 0; nt < 4; nt++) {
            int cn = wn0 + nt * 8 + g;
            bh[nt][0] = Bs2h[c][cn];
            bh[nt][1] = Bs2h[c + 4][cn];
            bl[nt][0] = Bs2l[c][cn];
            bl[nt][1] = Bs2l[c + 4][cn];
        }
#pragma unroll
        for (int mt = 0; mt < 4; mt++) {
            int row = wm0 + mt * 16 + g;
            unsigned ah[4], al[4];
            ah[0] = As2h[row][c];
            ah[1] = As2h[row + 8][c];
            ah[2] = As2h[row][c + 4];
            ah[3] = As2h[row + 8][c + 4];
            al[0] = As2l[row][c];
            al[1] = As2l[row + 8][c];
            al[2] = As2l[row][c + 4];
            al[3] = As2l[row + 8][c + 4];
#pragma unroll
            for (int nt = 0; nt < 4; nt++) {
                mma_f16(cacc[mt][nt], ah, bl[nt]);
                mma_f16(cacc[mt][nt], al, bh[nt]);
                mma_f16(cacc[mt][nt], ah, bh[nt]);
            }
        }
        __syncthreads();
    }

    const int b = m0 >> LOG2L;
    const int tbase = (m0 & (L_ - 1)) + wm0 + g;
#pragma unroll
    for (int nt = 0; nt < 4; nt++) {
        const int d0 = n0 + wn0 + nt * 8 + 2 * c;
        const float bi0 = bias[d0];
        const float bi1 = bias[d0 + 1];
        const size_t row0 = ((size_t)(b * D_ + d0) << LOG2L);
        const size_t row1 = row0 + L_;
#pragma unroll
        for (int mt = 0; mt < 4; mt++) {
            const int t = tbase + mt * 16;
            outT[row0 + t]     = cacc[mt][nt][0] + bi0;
            outT[row1 + t]     = cacc[mt][nt][1] + bi1;
            outT[row0 + t + 8] = cacc[mt][nt][2] + bi0;
            outT[row1 + t + 8] = cacc[mt][nt][3] + bi1;
        }
    }
}

// ---------------- complex helpers ----------------
__device__ __forceinline__ float2 cmul(float2 a, float2 b) {
    return make_float2(a.x * b.x - a.y * b.y, a.x * b.y + a.y * b.x);
}
__device__ __forceinline__ float2 cmulc(float2 a, float2 b) {   // a * conj(b)
    return make_float2(a.x * b.x + a.y * b.y, a.y * b.x - a.x * b.y);
}
__device__ __forceinline__ float2 cadd(float2 a, float2 b) { return make_float2(a.x + b.x, a.y + b.y); }
__device__ __forceinline__ float2 csub(float2 a, float2 b) { return make_float2(a.x - b.x, a.y - b.y); }

#define ZI(i) ((i) + ((i) >> 5))
#define XI(i) ((i) + ((i) >> 5))

#define BF_F(A, B, W) do { float2 _t = csub(A, B); A = cadd(A, B); B = cmul(_t, W); } while (0)
#define BF_I(A, B, W) do { float2 _bw = cmulc(B, W); B = csub(A, _bw); A = cadd(A, _bw); } while (0)

// ---------------- fused FFT-correlation + top-k + softmax + gather ----------------
// EXACT r14 champion: 128 threads, 16 pts/thread forward, half-size inverse.
__global__ __launch_bounds__(128)
void corr_attn_kernel() {
    __shared__ float2 tw[L_ / 2];
    __shared__ float2 z[L_ + L_ / 32];
    __shared__ float2 s[L_ + L_ / 32];
    __shared__ float  red_v[8];
    __shared__ int    red_i[8];

    const int tid = threadIdx.x;           // 0..127
    const int lane = tid & 31;
    const int warp = tid >> 5;              // 0..3
    const int bd = blockIdx.x;
    const size_t col = (size_t)bd << LOG2L;

    float2* zx = z + 1056;

    for (int i = tid; i < L_ / 2; i += 128) tw[i] = g_tw[i];

    float2 zr[16];
#pragma unroll
    for (int q = 0; q < 16; q++)
        zr[q] = make_float2(g_qT[col + tid + 128 * q], g_kT[col + tid + 128 * q]);
    __syncthreads();

    // ======== forward DIF, group 1: spans 1024/512/256/128 ========
#pragma unroll
    for (int q = 0; q < 8; q++) {
        float2 wv = tw[tid + 128 * q];
        BF_F(zr[q], zr[q + 8], wv);
    }
#pragma unroll
    for (int h = 0; h < 16; h += 8)
#pragma unroll
        for (int q = 0; q < 4; q++) {
            float2 wv = tw[(tid + 128 * q) << 1];
            BF_F(zr[h + q], zr[h + q + 4], wv);
        }
#pragma unroll
    for (int h = 0; h < 16; h += 4)
#pragma unroll
        for (int q = 0; q < 2; q++) {
            float2 wv = tw[(tid + 128 * q) << 2];
            BF_F(zr[h + q], zr[h + q + 2], wv);
        }
    {
        float2 wv = tw[tid << 3];
#pragma unroll
        for (int p = 0; p < 16; p += 2) BF_F(zr[p], zr[p + 1], wv);
    }
#pragma unroll
    for (int q = 0; q < 16; q++) s[ZI(tid + 128 * q)] = zr[q];
    __syncthreads();

    // ======== group 2: spans 64/32/16/8 ========
    const int c8 = (tid & 7) + (tid >> 3) * 128;
#pragma unroll
    for (int q = 0; q < 16; q++) zr[q] = s[ZI(c8 + 8 * q)];
#pragma unroll
    for (int q = 0; q < 8; q++) {
        float2 wv = tw[((tid & 7) + 8 * q) << 4];
        BF_F(zr[q], zr[q + 8], wv);
    }
#pragma unroll
    for (int h = 0; h < 16; h += 8)
#pragma unroll
        for (int q = 0; q < 4; q++) {
            float2 wv = tw[((tid & 7) + 8 * q) << 5];
            BF_F(zr[h + q], zr[h + q + 4], wv);
        }
#pragma unroll
    for (int h = 0; h < 16; h += 4)
#pragma unroll
        for (int q = 0; q < 2; q++) {
            float2 wv = tw[((tid & 7) + 8 * q) << 6];
            BF_F(zr[h + q], zr[h + q + 2], wv);
        }
    {
        float2 wv = tw[(tid & 7) << 7];
#pragma unroll
        for (int p = 0; p < 16; p += 2) BF_F(zr[p], zr[p + 1], wv);
    }
#pragma unroll
    for (int q = 0; q < 16; q++) s[ZI(c8 + 8 * q)] = zr[q];
    __syncthreads();

    // ======== group 3: spans 4/2/1 ========
    const int base16 = tid * 16;
#pragma unroll
    for (int q = 0; q < 16; q++) zr[q] = s[ZI(base16 + q)];
#pragma unroll
    for (int h = 0; h < 16; h += 8)
#pragma unroll
        for (int q = 0; q < 4; q++) {
            float2 wv = tw[q << 8];
            BF_F(zr[h + q], zr[h + q + 4], wv);
        }
#pragma unroll
    for (int h = 0; h < 16; h += 4)
#pragma unroll
        for (int q = 0; q < 2; q++) {
            float2 wv = tw[q << 9];
            BF_F(zr[h + q], zr[h + q + 2], wv);
        }
#pragma unroll
    for (int p = 0; p < 16; p += 2) {
        float2 a = zr[p], b = zr[p + 1];
        zr[p] = cadd(a, b);
        zr[p + 1] = csub(a, b);
    }
#pragma unroll
    for (int q = 0; q < 16; q++) s[ZI(base16 + q)] = zr[q];
    __syncthreads();

    // ======== cross-spectrum: s -> z ========
    const float scl = 0.25f / (float)L_;
#pragma unroll
    for (int it = 0; it < 16; it++) {
        int p = tid + 128 * it;
        int f = __brev((unsigned)p) >> 21;
        int fm = (L_ - f) & (L_ - 1);
        int pm = __brev((unsigned)fm) >> 21;
        float2 Zf = s[ZI(p)], Zm = s[ZI(pm)];
        float2 u = make_float2(Zf.x + Zm.x, Zf.y - Zm.y);
        float2 v = make_float2(Zf.x - Zm.x, -Zf.y - Zm.y);
        float2 pr = cmul(u, v);
        z[ZI(p)] = make_float2(-pr.y * scl, pr.x * scl);
    }
    __syncthreads();

    // ======== fused combine + inverse group A ========
    float2 X[8];
    {
        float2 Sp[16];
#pragma unroll
        for (int e = 0; e < 16; e++) Sp[e] = z[ZI(base16 + e)];
#pragma unroll
        for (int cc = 0; cc < 8; cc++) {
            int j = 8 * tid + cc;
            int k = __brev((unsigned)j) >> 22;
            float2 E = cadd(Sp[2 * cc], Sp[2 * cc + 1]);
            float2 Dd = csub(Sp[2 * cc], Sp[2 * cc + 1]);
            float2 O = cmulc(Dd, tw[k]);
            X[cc] = make_float2(E.x - O.y, E.y + O.x);
        }
#pragma unroll
        for (int p = 0; p < 8; p += 2) {
            float2 a = X[p], b = X[p + 1];
            X[p] = cadd(a, b);
            X[p + 1] = csub(a, b);
        }
#pragma unroll
        for (int h = 0; h < 8; h += 4)
#pragma unroll
            for (int q = 0; q < 2; q++) {
                float2 wv = tw[q << 9];
                BF_I(X[h + q], X[h + q + 2], wv);
            }
    }
    __syncthreads();
#pragma unroll
    for (int cc = 0; cc < 8; cc++) zx[XI(8 * tid + cc)] = X[cc];

    float* vcol = (float*)z;
    for (int i = tid; i < L_; i += 128) vcol[i] = g_vT[col + i];
    __syncthreads();

    // ======== inverse group B: spans 4/8/16 ========
    {
        const int c4b = (tid & 3) + (tid >> 2) * 32;
        float2 xr[8];
#pragma unroll
        for (int q = 0; q < 8; q++) xr[q] = zx[XI(c4b + 4 * q)];
        {
            float2 wv = tw[(tid & 3) << 8];
#pragma unroll
            for (int p = 0; p < 8; p += 2) BF_I(xr[p], xr[p + 1], wv);
        }
#pragma unroll
        for (int h = 0; h < 8; h += 4)
#pragma unroll
            for (int q = 0; q < 2; q++) {
                float2 wv = tw[((tid & 3) + 4 * q) << 7];
                BF_I(xr[h + q], xr[h + q + 2], wv);
            }
#pragma unroll
        for (int q = 0; q < 4; q++) {
            float2 wv = tw[((tid & 3) + 4 * q) << 6];
            BF_I(xr[q], xr[q + 4], wv);
        }
#pragma unroll
        for (int q = 0; q < 8; q++) zx[XI(c4b + 4 * q)] = xr[q];
    }
    __syncthreads();

    // ======== inverse group C: spans 32/64/128 ========
    {
        const int c32b = (tid & 31) + (tid >> 5) * 256;
        float2 xr[8];
#pragma unroll
        for (int q = 0; q < 8; q++) xr[q] = zx[XI(c32b + 32 * q)];
        {
            float2 wv = tw[(tid & 31) << 5];
#pragma unroll
            for (int p = 0; p < 8; p += 2) BF_I(xr[p], xr[p + 1], wv);
        }
#pragma unroll
        for (int h = 0; h < 8; h += 4)
#pragma unroll
            for (int q = 0; q < 2; q++) {
                float2 wv = tw[((tid & 31) + 32 * q) << 4];
                BF_I(xr[h + q], xr[h + q + 2], wv);
            }
#pragma unroll
        for (int q = 0; q < 4; q++) {
            float2 wv = tw[((tid & 31) + 32 * q) << 3];
            BF_I(xr[q], xr[q + 4], wv);
        }
#pragma unroll
        for (int q = 0; q < 8; q++) zx[XI(c32b + 32 * q)] = xr[q];
    }
    __syncthreads();

    // ======== inverse group D: spans 256/512 (registers; feeds top-k) ========
    float2 xr[8];
#pragma unroll
    for (int q = 0; q < 8; q++) xr[q] = zx[XI(tid + 128 * q)];
#pragma unroll
    for (int h = 0; h < 8; h += 4)
#pragma unroll
        for (int q = 0; q < 2; q++) {
            float2 wv = tw[(tid + 128 * q) << 2];
            BF_I(xr[h + q], xr[h + q + 2], wv);
        }
#pragma unroll
    for (int q = 0; q < 4; q++) {
        float2 wv = tw[(tid + 128 * q) << 1];
        BF_I(xr[q], xr[q + 4], wv);
    }

    // ---- top-15; idx = 2*tid + 256*q + comp ----
    float rv[16];
#pragma unroll
    for (int q = 0; q < 8; q++) { rv[2 * q] = xr[q].x; rv[2 * q + 1] = xr[q].y; }

    float wsel[KTOP];
    int isel[KTOP];
#pragma unroll 1
    for (int rnd = 0; rnd < KTOP; rnd++) {
        float best = rv[0];
        int bq = 0;
#pragma unroll
        for (int q = 1; q < 16; q++)
            if (rv[q] > best) { best = rv[q]; bq = q; }
        int bi = 2 * tid + 256 * (bq >> 1) + (bq & 1);
#pragma unroll
        for (int off = 16; off > 0; off >>= 1) {
            float ov = __shfl_xor_sync(0xffffffffu, best, off);
            int oi = __shfl_xor_sync(0xffffffffu, bi, off);
            if (ov > best || (ov == best && oi < bi)) { best = ov; bi = oi; }
        }
        const int slot = (rnd & 1) * 4;
        if (lane == 0) { red_v[slot + warp] = best; red_i[slot + warp] = bi; }
        __syncthreads();
        float gb = red_v[slot];
        int gi = red_i[slot];
#pragma unroll
        for (int ww = 1; ww < 4; ww++) {
            float ov = red_v[slot + ww];
            int oi = red_i[slot + ww];
            if (ov > gb || (ov == gb && oi < gi)) { gb = ov; gi = oi; }
        }
        wsel[rnd] = gb;
        isel[rnd] = gi;
#pragma unroll
        for (int q = 0; q < 8; q++) {
            if (gi == 2 * tid + 256 * q)     rv[2 * q]     = -FLT_MAX;
            if (gi == 2 * tid + 256 * q + 1) rv[2 * q + 1] = -FLT_MAX;
        }
    }

    // ---- softmax ----
    float m = wsel[0];
#pragma unroll
    for (int k = 1; k < KTOP; k++) m = fmaxf(m, wsel[k]);
    float sum = 0.0f;
    float wnorm[KTOP];
#pragma unroll
    for (int k = 0; k < KTOP; k++) { float e = __expf(wsel[k] - m); wnorm[k] = e; sum += e; }
    const float inv = 1.0f / sum;
#pragma unroll
    for (int k = 0; k < KTOP; k++) wnorm[k] *= inv;

    // ---- gather ----
    for (int l = tid; l < L_; l += 128) {
        float acc = 0.0f;
#pragma unroll
        for (int k = 0; k < KTOP; k++)
            acc = fmaf(wnorm[k], vcol[(l + isel[k]) & (L_ - 1)], acc);
        g_AT[col + l] = acc;
    }
}

// ---------------- transpose (B, D, L) -> (B, L, D) ----------------
__global__ void transpose_kernel(float* __restrict__ A) {
    __shared__ float tile[32][33];
    const int b = blockIdx.z;
    const int l0 = blockIdx.x * 32;
    const int d0 = blockIdx.y * 32;
    const int tx = threadIdx.x, ty = threadIdx.y;
#pragma unroll
    for (int r = 0; r < 32; r += 8)
        tile[ty + r][tx] = g_AT[((size_t)(b * D_ + d0 + ty + r) << LOG2L) + l0 + tx];
    __syncthreads();
#pragma unroll
    for (int r = 0; r < 32; r += 8)
        A[((size_t)(b * L_ + l0 + ty + r)) * D_ + d0 + tx] = tile[tx][ty + r];
}

// ---------------- launch ----------------
extern "C" void kernel_launch(void* const* d_in, const int* in_sizes, int n_in,
                              void* d_out, int out_size) {
    const float* Q   = (const float*)d_in[0];
    const float* K   = (const float*)d_in[1];
    const float* V   = (const float*)d_in[2];
    const float* WQw = (const float*)d_in[3];
    const float* WQb = (const float*)d_in[4];
    const float* WKw = (const float*)d_in[5];
    const float* WKb = (const float*)d_in[6];
    const float* WVw = (const float*)d_in[7];
    const float* WVb = (const float*)d_in[8];
    float* out = (float*)d_out;

    // corr only: max smem carveout so up to 5 CTAs (41.25KB each) fit per SM.
    // No launch-bounds clamp (the r12 mistake) -> no register spills.
    cudaFuncSetAttribute(corr_attn_kernel,
                         cudaFuncAttributePreferredSharedMemoryCarveout, 100);

    twiddle_init_kernel<<<4, 256>>>();

    dim3 ggrid(B_ * L_ / 128, D_ / 128, 3);   // (128, 4, 3)
    gemm3_fp16_kernel<<<ggrid, 256>>>(Q, K, V, WQw, WKw, WVw, WQb, WKb, WVb);

    corr_attn_kernel<<<B_ * D_, 128>>>();

    dim3 tgrid(L_ / 32, D_ / 32, B_);         // (64, 16, 8)
    transpose_kernel<<<tgrid, dim3(32, 8)>>>(out);
}